// round 8
// baseline (speedup 1.0000x reference)
#include <cuda_runtime.h>
#include <cuda_fp16.h>
#include <cstdint>

// Problem constants
#define NN   8
#define CC   256
#define HH   64
#define WW   64
#define OC   256
#define KK   9
#define PIX  4096

// Scratch
__device__ __half g_xh[NN * PIX * CC];      // x as NHWC fp16
__device__ __half g_wh[72 * OC * 32];       // weights fp16 [chunk][oc][32 phys]

// sigma: logical l (0..31) <-> physical p: p = t*8 + kk*4 + h*2 + b
// where l = kk*16 + 2t + b + 8h

__device__ __forceinline__ void cp_async16(uint32_t saddr, const void* g) {
    asm volatile("cp.async.cg.shared.global [%0], [%1], 16;"
                 :: "r"(saddr), "l"(g) : "memory");
}

// ---------------------------------------------------------------------------
// Kernel 1: NCHW fp32 -> NHWC fp16
// ---------------------------------------------------------------------------
__global__ void k_transpose_x(const float* __restrict__ x)
{
    __shared__ float tile[32 * 33];
    const int n  = blockIdx.z;
    const int p0 = blockIdx.x * 32;
    const int c0 = blockIdx.y * 32;
    const int t  = threadIdx.x;
    {
        int c  = t >> 3;
        int p4 = (t & 7) << 2;
        float4 v = *(const float4*)&x[((size_t)(n * CC + c0 + c)) * PIX + p0 + p4];
        tile[c * 33 + p4 + 0] = v.x;
        tile[c * 33 + p4 + 1] = v.y;
        tile[c * 33 + p4 + 2] = v.z;
        tile[c * 33 + p4 + 3] = v.w;
    }
    __syncthreads();
    {
        int p  = t >> 3;
        int c4 = (t & 7) << 2;
        __half2 h0 = __floats2half2_rn(tile[(c4 + 0) * 33 + p], tile[(c4 + 1) * 33 + p]);
        __half2 h1 = __floats2half2_rn(tile[(c4 + 2) * 33 + p], tile[(c4 + 3) * 33 + p]);
        uint2 o = { *(uint32_t*)&h0, *(uint32_t*)&h1 };
        *(uint2*)&g_xh[((size_t)(n * PIX + p0 + p)) * CC + c0 + c4] = o;
    }
}

// ---------------------------------------------------------------------------
// Kernel 2: weight [oc][c][k] -> fp16 [chunk72][oc][32 phys], sigma-permuted
// ---------------------------------------------------------------------------
__global__ void k_prep_w(const float* __restrict__ w)
{
    int idx = blockIdx.x * 256 + threadIdx.x;   // over 72*256*32
    int p   = idx & 31;
    int oc  = (idx >> 5) & 255;
    int ch  = idx >> 13;
    int k   = ch >> 3;
    int c0  = (ch & 7) << 5;
    int t  = p >> 3, q = p & 7;
    int kk = q >> 2, h = (q >> 1) & 1, b = q & 1;
    int l  = kk * 16 + 2 * t + b + 8 * h;
    g_wh[idx] = __float2half_rn(w[((size_t)oc * CC + c0 + l) * KK + k]);
}

// ---------------------------------------------------------------------------
// Kernel 3: fused deformable gather + fp16 mma, software-pipelined so the
// gather LDG latency hides under the mma of the previous chunk.
// CTA: 512 threads, tile M=128 x N=256 x BK=32; 16 warps 4(M)x4(N).
// ---------------------------------------------------------------------------
#define NCHUNK 72
#define AHALF  (128 * 32)
#define BHALF  (256 * 32)

struct Gath { uint4 v[4]; };   // 4 corners x 8 fp16

__device__ __forceinline__ void gather_params(
    int k, int row, int mb, int n, const float* __restrict__ offset,
    float* gw, int* go)
{
    const int ky = k / 3 - 1, kx = k - (k / 3) * 3 - 1;
    const float* offp = offset + (size_t)(n * 18 + 2 * k) * PIX + mb;
    int oh = (mb + row) >> 6, ow = (mb + row) & 63;
    float y  = (float)(oh + ky) + offp[row];
    float xx = (float)(ow + kx) + offp[row + PIX];
    float y0 = floorf(y), x0 = floorf(xx);
#pragma unroll
    for (int d = 0; d < 4; ++d) {
        float yi = y0 + (float)(d >> 1);
        float xi = x0 + (float)(d & 1);
        float wv = (1.0f - fabsf(y - yi)) * (1.0f - fabsf(xx - xi));
        bool valid = (yi >= 0.0f) && (yi <= 63.0f) &&
                     (xi >= 0.0f) && (xi <= 63.0f);
        int yc = (int)fminf(fmaxf(yi, 0.0f), 63.0f);
        int xc = (int)fminf(fmaxf(xi, 0.0f), 63.0f);
        gw[d] = valid ? wv : 0.0f;
        go[d] = ((n * HH + yc) * WW + xc) << 8;
    }
}

__device__ __forceinline__ Gath gather_load(int c0, int u, const int* go)
{
    Gath g;
#pragma unroll
    for (int d = 0; d < 4; ++d)
        g.v[d] = *(const uint4*)(g_xh + go[d] + c0 + u * 8);
    return g;
}

__device__ __forceinline__ void combine_sts(
    const Gath& g, const float* gw, __half* __restrict__ As, int row, int u)
{
    float a[8];
#pragma unroll
    for (int q = 0; q < 4; ++q) {
        const uint32_t* w0p = (const uint32_t*)&g.v[0];
        const uint32_t* w1p = (const uint32_t*)&g.v[1];
        const uint32_t* w2p = (const uint32_t*)&g.v[2];
        const uint32_t* w3p = (const uint32_t*)&g.v[3];
        float2 f0 = __half22float2(*(const __half2*)&w0p[q]);
        float2 f1 = __half22float2(*(const __half2*)&w1p[q]);
        float2 f2 = __half22float2(*(const __half2*)&w2p[q]);
        float2 f3 = __half22float2(*(const __half2*)&w3p[q]);
        a[2*q]   = gw[0]*f0.x + gw[1]*f1.x + gw[2]*f2.x + gw[3]*f3.x;
        a[2*q+1] = gw[0]*f0.y + gw[1]*f1.y + gw[2]*f2.y + gw[3]*f3.y;
    }
    int jrot = (row >> 1) & 3;
#pragma unroll
    for (int j = 0; j < 4; ++j) {
        int jj = (j + jrot) & 3;
        __half2 hv = __floats2half2_rn(a[2*jj], a[2*jj + 1]);
        *(__half2*)(As + row * 32 + u * 2 + jj * 8) = hv;
    }
}

__global__ __launch_bounds__(512, 1)
void k_dconv_mma(const float* __restrict__ offset, float* __restrict__ out)
{
    extern __shared__ float sm[];
    __half* smh = (__half*)sm;
    __half* Asb[2] = { smh,             smh + AHALF };
    __half* Bsb[2] = { smh + 2 * AHALF, smh + 2 * AHALF + BHALF };

    const int tid  = threadIdx.x;
    const int lane = tid & 31;
    const int wid  = tid >> 5;
    const int bx   = blockIdx.x;
    const int n    = bx >> 5;
    const int mb   = (bx & 31) << 7;

    const int row = tid >> 2;          // pixel within tile
    const int u   = tid & 3;           // c-group

    const int wm  = (wid & 3) << 5;
    const int wn  = (wid >> 2) << 6;
    const int gid = lane >> 2;
    const int tig = lane & 3;

    float acc[2][8][4];
#pragma unroll
    for (int mi = 0; mi < 2; ++mi)
#pragma unroll
        for (int ni = 0; ni < 8; ++ni)
#pragma unroll
            for (int q = 0; q < 4; ++q) acc[mi][ni][q] = 0.0f;

    float gw[4]; int go[4];

    // prologue: build chunk 0
    {
        gather_params(0, row, mb, n, offset, gw, go);
        Gath v = gather_load(0, u, go);
        uint32_t bbase = (uint32_t)__cvta_generic_to_shared(Bsb[0]);
        const __half* wb = g_wh;
#pragma unroll
        for (int r = 0; r < 2; ++r) {
            int idx = tid + (r << 9);
            cp_async16(bbase + (uint32_t)idx * 16, wb + idx * 8);
        }
        combine_sts(v, gw, Asb[0], row, u);
        asm volatile("cp.async.wait_all;" ::: "memory");
        __syncthreads();
    }

    for (int i = 0; i < NCHUNK; ++i) {
        const bool pf = (i + 1 < NCHUNK);
        Gath v;
        if (pf) {
            const int i1 = i + 1;
            if ((i1 & 7) == 0)
                gather_params(i1 >> 3, row, mb, n, offset, gw, go);
            v = gather_load((i1 & 7) << 5, u, go);
            // B(i+1) via cp.async, lands during mma(i)
            uint32_t bbase = (uint32_t)__cvta_generic_to_shared(Bsb[i1 & 1]);
            const __half* wb = g_wh + (size_t)i1 * (OC * 32);
#pragma unroll
            for (int r = 0; r < 2; ++r) {
                int idx = tid + (r << 9);
                cp_async16(bbase + (uint32_t)idx * 16, wb + idx * 8);
            }
        }

        // ---- mma on chunk i (hides gather latency of i+1) ----
        {
            const __half* A = Asb[i & 1];
            const __half* B = Bsb[i & 1];
            uint32_t afr[4][4];
#pragma unroll
            for (int r4 = 0; r4 < 4; ++r4) {
                const uint4 av = *(const uint4*)(A + (wm + gid + r4 * 8) * 32 + tig * 8);
                afr[r4][0] = av.x; afr[r4][1] = av.y; afr[r4][2] = av.z; afr[r4][3] = av.w;
            }
#pragma unroll
            for (int ni = 0; ni < 8; ++ni) {
                const uint4 bv = *(const uint4*)(B + (wn + ni * 8 + gid) * 32 + tig * 8);
                const uint32_t bfr[4] = { bv.x, bv.y, bv.z, bv.w };
#pragma unroll
                for (int kk = 0; kk < 2; ++kk) {
#pragma unroll
                    for (int mi = 0; mi < 2; ++mi) {
                        asm volatile(
                            "mma.sync.aligned.m16n8k16.row.col.f32.f16.f16.f32 "
                            "{%0,%1,%2,%3}, {%4,%5,%6,%7}, {%8,%9}, {%0,%1,%2,%3};"
                            : "+f"(acc[mi][ni][0]), "+f"(acc[mi][ni][1]),
                              "+f"(acc[mi][ni][2]), "+f"(acc[mi][ni][3])
                            : "r"(afr[2*mi][2*kk]),   "r"(afr[2*mi+1][2*kk]),
                              "r"(afr[2*mi][2*kk+1]), "r"(afr[2*mi+1][2*kk+1]),
                              "r"(bfr[2*kk]), "r"(bfr[2*kk+1]));
                    }
                }
            }
        }

        if (pf)
            combine_sts(v, gw, Asb[(i + 1) & 1], row, u);

        asm volatile("cp.async.wait_all;" ::: "memory");
        __syncthreads();
    }

    // ---- epilogue: two 128-oc halves staged [oc][m] (pitch 132) ----
    float* st = sm;
#pragma unroll
    for (int h = 0; h < 2; ++h) {
        __syncthreads();
        if ((wn >> 7) == h) {
            int wnl = wn & 127;
#pragma unroll
            for (int mi = 0; mi < 2; ++mi) {
                int row0 = wm + (mi << 4) + gid;
#pragma unroll
                for (int ni = 0; ni < 8; ++ni) {
                    int col = wnl + (ni << 3) + (tig << 1);
                    st[ col      * 132 + row0    ] = acc[mi][ni][0];
                    st[(col + 1) * 132 + row0    ] = acc[mi][ni][1];
                    st[ col      * 132 + row0 + 8] = acc[mi][ni][2];
                    st[(col + 1) * 132 + row0 + 8] = acc[mi][ni][3];
                }
            }
        }
        __syncthreads();
        float* ob = out + ((size_t)n * OC + h * 128) * PIX + mb;
#pragma unroll
        for (int it = 0; it < 8; ++it) {
            int idx = tid + (it << 9);
            int oc  = idx >> 5;
            int m4  = (idx & 31) << 2;
            *(float4*)(ob + (size_t)oc * PIX + m4) =
                *(const float4*)(st + oc * 132 + m4);
        }
    }
}

// ---------------------------------------------------------------------------
extern "C" void kernel_launch(void* const* d_in, const int* in_sizes, int n_in,
                              void* d_out, int out_size)
{
    const float* x      = (const float*)d_in[0];   // (8,256,64,64)
    const float* offset = (const float*)d_in[1];   // (8,18,64,64)
    const float* weight = (const float*)d_in[2];   // (256,256,3,3)
    float* out = (float*)d_out;                    // (8,256,64,64)

    const int dyn_smem = 128 * 132 * sizeof(float);   // 67584 B
    cudaFuncSetAttribute(k_dconv_mma,
                         cudaFuncAttributeMaxDynamicSharedMemorySize, dyn_smem);

    k_transpose_x<<<dim3(PIX / 32, CC / 32, NN), 256>>>(x);
    k_prep_w<<<(72 * OC * 32) / 256, 256>>>(weight);
    k_dconv_mma<<<256, 512, dyn_smem>>>(offset, out);
}

// round 10
// speedup vs baseline: 1.3128x; 1.3128x over previous
#include <cuda_runtime.h>
#include <cuda_fp16.h>
#include <cstdint>

// Problem constants
#define NN   8
#define CC   256
#define HH   64
#define WW   64
#define OC   256
#define KK   9
#define PIX  4096

// Scratch
__device__ float  g_xt[NN * PIX * CC];      // x as NHWC fp32
__device__ __half g_wh[72 * OC * 32];       // weights fp16 [chunk][oc][32 phys]

// sigma: logical l (0..31) <-> physical p: p = t*8 + kk*4 + h*2 + b
// where l = kk*16 + 2t + b + 8h

__device__ __forceinline__ void cp_async16(uint32_t saddr, const void* g) {
    asm volatile("cp.async.cg.shared.global [%0], [%1], 16;"
                 :: "r"(saddr), "l"(g) : "memory");
}

// ---------------------------------------------------------------------------
// Kernel 1: NCHW -> NHWC transpose (fp32)
// ---------------------------------------------------------------------------
__global__ void k_transpose_x(const float* __restrict__ x)
{
    __shared__ float tile[32 * 33];
    const int n  = blockIdx.z;
    const int p0 = blockIdx.x * 32;
    const int c0 = blockIdx.y * 32;
    const int t  = threadIdx.x;
    {
        int c  = t >> 3;
        int p4 = (t & 7) << 2;
        float4 v = *(const float4*)&x[((size_t)(n * CC + c0 + c)) * PIX + p0 + p4];
        tile[c * 33 + p4 + 0] = v.x;
        tile[c * 33 + p4 + 1] = v.y;
        tile[c * 33 + p4 + 2] = v.z;
        tile[c * 33 + p4 + 3] = v.w;
    }
    __syncthreads();
    {
        int p  = t >> 3;
        int c4 = (t & 7) << 2;
        float4 o;
        o.x = tile[(c4 + 0) * 33 + p];
        o.y = tile[(c4 + 1) * 33 + p];
        o.z = tile[(c4 + 2) * 33 + p];
        o.w = tile[(c4 + 3) * 33 + p];
        *(float4*)&g_xt[((size_t)(n * PIX + p0 + p)) * CC + c0 + c4] = o;
    }
}

// ---------------------------------------------------------------------------
// Kernel 2: weight [oc][c][k] -> fp16 [chunk72][oc][32 phys], sigma-permuted
// ---------------------------------------------------------------------------
__global__ void k_prep_w(const float* __restrict__ w)
{
    int idx = blockIdx.x * 256 + threadIdx.x;   // over 72*256*32
    int p   = idx & 31;
    int oc  = (idx >> 5) & 255;
    int ch  = idx >> 13;
    int k   = ch >> 3;
    int c0  = (ch & 7) << 5;
    int t  = p >> 3, q = p & 7;
    int kk = q >> 2, h = (q >> 1) & 1, b = q & 1;
    int l  = kk * 16 + 2 * t + b + 8 * h;
    g_wh[idx] = __float2half_rn(w[((size_t)oc * CC + c0 + l) * KK + k]);
}

// ---------------------------------------------------------------------------
// Kernel 3: fused deformable gather + fp16 m16n8k16 mma GEMM
// CTA: 256 threads, tile M=64 x N=256 x BK=32; 8 warps 2(M)x4(N), warp 32x64.
// 2 CTAs/SM so build/barrier phases of one CTA overlap mma of the other.
// grid 512 = 8 n * 64 mtiles.
// ---------------------------------------------------------------------------
#define NCHUNK 72
#define AHALF  (64 * 32)      // halfs per A buffer
#define BHALF  (256 * 32)
#define STP    68             // epilogue stage pitch (floats); 68*4=272=17*16 B

__device__ __forceinline__ void build_tiles(
    int i, int tid, int n, int mb,
    const float* __restrict__ offset,
    __half* __restrict__ As, __half* __restrict__ Bs,
    float* gw, int* go)
{
    const int k   = i >> 3;
    const int c0  = (i & 7) << 5;
    const int row = tid >> 2;        // 0..63 (pixel within tile)
    const int u   = tid & 3;         // logical c-group (8 c each)

    // B tile via cp.async: 256 oc x 64 B (pre-permuted fp16), 4 chunks/thread
    {
        const __half* wb = g_wh + (size_t)i * (OC * 32);
        uint32_t bbase = (uint32_t)__cvta_generic_to_shared(Bs);
#pragma unroll
        for (int r = 0; r < 4; ++r) {
            int idx = tid + (r << 8);               // 0..1023 16B chunks
            cp_async16(bbase + (uint32_t)idx * 16, wb + idx * 8);
        }
    }

    if ((i & 7) == 0) {   // new k-tap: recompute private bilinear params
        const int ky = k / 3 - 1, kx = k - (k / 3) * 3 - 1;
        const float* offp = offset + (size_t)(n * 18 + 2 * k) * PIX + mb;
        int oh = (mb + row) >> 6, ow = (mb + row) & 63;
        float y  = (float)(oh + ky) + offp[row];
        float xx = (float)(ow + kx) + offp[row + PIX];
        float y0 = floorf(y), x0 = floorf(xx);
#pragma unroll
        for (int d = 0; d < 4; ++d) {
            float yi = y0 + (float)(d >> 1);
            float xi = x0 + (float)(d & 1);
            float wv = (1.0f - fabsf(y - yi)) * (1.0f - fabsf(xx - xi));
            bool valid = (yi >= 0.0f) && (yi <= 63.0f) &&
                         (xi >= 0.0f) && (xi <= 63.0f);
            int yc = (int)fminf(fmaxf(yi, 0.0f), 63.0f);
            int xc = (int)fminf(fmaxf(xi, 0.0f), 63.0f);
            gw[d] = valid ? wv : 0.0f;
            go[d] = ((n * HH + yc) * WW + xc) << 8;
        }
    }

    // gather 8 contiguous logical c, bilinear combine in fp32
    float a[8];
    {
        const float* b0 = g_xt + go[0] + c0 + u * 8;
        const float* b1 = g_xt + go[1] + c0 + u * 8;
        const float* b2 = g_xt + go[2] + c0 + u * 8;
        const float* b3 = g_xt + go[3] + c0 + u * 8;
        float w0 = gw[0], w1 = gw[1], w2 = gw[2], w3 = gw[3];
#pragma unroll
        for (int hlf = 0; hlf < 2; ++hlf) {
            float4 v0 = *(const float4*)(b0 + hlf * 4);
            float4 v1 = *(const float4*)(b1 + hlf * 4);
            float4 v2 = *(const float4*)(b2 + hlf * 4);
            float4 v3 = *(const float4*)(b3 + hlf * 4);
            a[hlf*4+0] = w0*v0.x + w1*v1.x + w2*v2.x + w3*v3.x;
            a[hlf*4+1] = w0*v0.y + w1*v1.y + w2*v2.y + w3*v3.y;
            a[hlf*4+2] = w0*v0.z + w1*v1.z + w2*v2.z + w3*v3.z;
            a[hlf*4+3] = w0*v0.w + w1*v1.w + w2*v2.w + w3*v3.w;
        }
    }
    // sigma-scatter as half2, rotation keeps STS conflict-free
    int jrot = (row >> 1) & 3;
#pragma unroll
    for (int j = 0; j < 4; ++j) {
        int jj = (j + jrot) & 3;
        __half2 hv = __floats2half2_rn(a[2*jj], a[2*jj + 1]);
        *(__half2*)(As + row * 32 + u * 2 + jj * 8) = hv;
    }
}

__global__ __launch_bounds__(256, 2)
void k_dconv_mma(const float* __restrict__ offset, float* __restrict__ out)
{
    extern __shared__ float sm[];
    __half* smh = (__half*)sm;
    __half* Asb[2] = { smh,             smh + AHALF };
    __half* Bsb[2] = { smh + 2 * AHALF, smh + 2 * AHALF + BHALF };

    const int tid  = threadIdx.x;
    const int lane = tid & 31;
    const int wid  = tid >> 5;
    const int bx   = blockIdx.x;
    const int n    = bx >> 6;
    const int mb   = (bx & 63) << 6;

    const int wm  = (wid & 1) << 5;     // 0,32
    const int wn  = (wid >> 1) << 6;    // 0,64,128,192
    const int gid = lane >> 2;
    const int tig = lane & 3;

    float acc[2][8][4];
#pragma unroll
    for (int mi = 0; mi < 2; ++mi)
#pragma unroll
        for (int ni = 0; ni < 8; ++ni)
#pragma unroll
            for (int q = 0; q < 4; ++q) acc[mi][ni][q] = 0.0f;

    float gw[4]; int go[4];
    build_tiles(0, tid, n, mb, offset, Asb[0], Bsb[0], gw, go);
    asm volatile("cp.async.wait_all;" ::: "memory");
    __syncthreads();

    for (int i = 0; i < NCHUNK; ++i) {
        if (i + 1 < NCHUNK)
            build_tiles(i + 1, tid, n, mb, offset,
                        Asb[(i + 1) & 1], Bsb[(i + 1) & 1], gw, go);

        const __half* A = Asb[i & 1];
        const __half* B = Bsb[i & 1];

        uint32_t afr[4][4];
#pragma unroll
        for (int r4 = 0; r4 < 4; ++r4) {
            const uint4 av = *(const uint4*)(A + (wm + gid + r4 * 8) * 32 + tig * 8);
            afr[r4][0] = av.x; afr[r4][1] = av.y; afr[r4][2] = av.z; afr[r4][3] = av.w;
        }
#pragma unroll
        for (int ni = 0; ni < 8; ++ni) {
            const uint4 bv = *(const uint4*)(B + (wn + ni * 8 + gid) * 32 + tig * 8);
            const uint32_t bfr[4] = { bv.x, bv.y, bv.z, bv.w };
#pragma unroll
            for (int kk = 0; kk < 2; ++kk) {
#pragma unroll
                for (int mi = 0; mi < 2; ++mi) {
                    asm volatile(
                        "mma.sync.aligned.m16n8k16.row.col.f32.f16.f16.f32 "
                        "{%0,%1,%2,%3}, {%4,%5,%6,%7}, {%8,%9}, {%0,%1,%2,%3};"
                        : "+f"(acc[mi][ni][0]), "+f"(acc[mi][ni][1]),
                          "+f"(acc[mi][ni][2]), "+f"(acc[mi][ni][3])
                        : "r"(afr[2*mi][2*kk]),   "r"(afr[2*mi+1][2*kk]),
                          "r"(afr[2*mi][2*kk+1]), "r"(afr[2*mi+1][2*kk+1]),
                          "r"(bfr[2*kk]), "r"(bfr[2*kk+1]));
                }
            }
        }
        asm volatile("cp.async.wait_all;" ::: "memory");
        __syncthreads();
    }

    // ---- epilogue: two 128-oc halves staged [oc][m] (pitch STP=68) ----
    float* st = sm;     // 128*68*4 = 34816 B <= 40960 dyn
#pragma unroll
    for (int h = 0; h < 2; ++h) {
        __syncthreads();
        if ((wn >> 7) == h) {
            int wnl = wn & 127;
#pragma unroll
            for (int mi = 0; mi < 2; ++mi) {
                int row0 = wm + (mi << 4) + gid;
#pragma unroll
                for (int ni = 0; ni < 8; ++ni) {
                    int col = wnl + (ni << 3) + (tig << 1);
                    st[ col      * STP + row0    ] = acc[mi][ni][0];
                    st[(col + 1) * STP + row0    ] = acc[mi][ni][1];
                    st[ col      * STP + row0 + 8] = acc[mi][ni][2];
                    st[(col + 1) * STP + row0 + 8] = acc[mi][ni][3];
                }
            }
        }
        __syncthreads();
        float* ob = out + ((size_t)n * OC + h * 128) * PIX + mb;
#pragma unroll
        for (int it = 0; it < 8; ++it) {
            int idx = tid + (it << 8);       // 0..2047 over 128 oc x 16 float4
            int oc  = idx >> 4;
            int m4  = (idx & 15) << 2;
            *(float4*)(ob + (size_t)oc * PIX + m4) =
                *(const float4*)(st + oc * STP + m4);
        }
    }
}

// ---------------------------------------------------------------------------
extern "C" void kernel_launch(void* const* d_in, const int* in_sizes, int n_in,
                              void* d_out, int out_size)
{
    const float* x      = (const float*)d_in[0];   // (8,256,64,64)
    const float* offset = (const float*)d_in[1];   // (8,18,64,64)
    const float* weight = (const float*)d_in[2];   // (256,256,3,3)
    float* out = (float*)d_out;                    // (8,256,64,64)

    const int dyn_smem = 40960;   // tiles 2*(4KB+16KB)=40KB >= stage 34.8KB
    cudaFuncSetAttribute(k_dconv_mma,
                         cudaFuncAttributeMaxDynamicSharedMemorySize, dyn_smem);

    k_transpose_x<<<dim3(PIX / 32, CC / 32, NN), 256>>>(x);
    k_prep_w<<<(72 * OC * 32) / 256, 256>>>(weight);
    k_dconv_mma<<<512, 256, dyn_smem>>>(offset, out);
}